// round 16
// baseline (speedup 1.0000x reference)
#include <cuda_runtime.h>
#include <cuda_fp16.h>

// ---------------------------------------------------------------------------
// GNN forward: 3 layers of COO SpMM + gating, mean over layers.
// R15: layer kernels are L2-bandwidth-bound (~30us floor at 384B/row gathers),
// so halve the gather stream for layers 2&3 by keeping an fp16 shadow copy of
// ego (gather operand only; gating own-row reads, accumulation, and all stored
// fp32 state stay fp32). Layer 1 gathers fp32 X exactly. Gathers vectorized
// (one LDG.128 / LDG.64 per edge on lanes 0-23).
// ---------------------------------------------------------------------------

namespace {
constexpr int NN  = 50000;     // nodes
constexpr int EE  = 800000;    // edges
constexpr int D   = 96;        // embedding dim
constexpr int D4  = D / 4;     // 24 float4 (or 24 uint2-of-half) per row
constexpr int SB  = 256;                       // scan block
constexpr int NSB = (NN + SB - 1) / SB;        // 196 scan blocks
}

// Scratch (allocation-free rule: __device__ globals only).
__device__ __align__(16) float g_bufA[(size_t)NN * D];   // ego1 fp32
__device__ __align__(16) float g_bufB[(size_t)NN * D];   // ego2 fp32
__device__ __align__(16) uint2 g_h16A[(size_t)NN * D4];  // ego2 fp16 shadow
__device__ __align__(16) uint2 g_h16B[(size_t)NN * D4];  // ego1 fp16 shadow
__device__ int   g_row_ptr[NN + 1];
__device__ int   g_fill[NN];          // counts, then fill cursors
__device__ int   g_scan[NN];          // block-local inclusive scans
__device__ int   g_bsum[NSB];         // per-block sums -> exclusive offsets
__device__ int   g_ecol[EE];
__device__ float g_eval[EE];
__device__ int   g_idx64;             // 1 if rows/cols are int64, 0 if int32

__device__ __forceinline__ int load_idx(const void* p, int e) {
    return g_idx64 ? (int)reinterpret_cast<const long long*>(p)[e]
                   : reinterpret_cast<const int*>(p)[e];
}

// Zero histogram counters; thread 0 also detects index width (JAX silently
// downcasts int64->int32 when x64 is off; int64 indices < 50000 have zero
// high words, random int32 data at odd u32 slots is ~never all zero).
__global__ void zero_detect_kernel(const unsigned int* __restrict__ rows_u32) {
    int i = blockIdx.x * blockDim.x + threadIdx.x;
    if (i < NN) g_fill[i] = 0;
    if (i == 0) {
        int is64 = 1;
        for (int k = 0; k < 64; k++)
            if (rows_u32[2 * k + 1] != 0u) { is64 = 0; break; }
        g_idx64 = is64;
    }
}

__global__ void hist_kernel(const void* __restrict__ rows_raw) {
    int e = blockIdx.x * blockDim.x + threadIdx.x;
    if (e < EE) atomicAdd(&g_fill[load_idx(rows_raw, e)], 1);
}

// Phase 1: block-local inclusive scan of counts; per-block totals to g_bsum.
__global__ __launch_bounds__(SB)
void scan_phase1() {
    __shared__ int sh[SB];
    const int t = threadIdx.x;
    const int i = blockIdx.x * SB + t;
    sh[t] = (i < NN) ? g_fill[i] : 0;
    __syncthreads();
#pragma unroll
    for (int off = 1; off < SB; off <<= 1) {
        int u = (t >= off) ? sh[t - off] : 0;
        __syncthreads();
        if (t >= off) sh[t] += u;
        __syncthreads();
    }
    if (i < NN) g_scan[i] = sh[t];
    if (t == SB - 1) g_bsum[blockIdx.x] = sh[t];
}

// Phase 2: exclusive scan of the NSB block sums (single tiny block).
__global__ __launch_bounds__(SB)
void scan_phase2() {
    __shared__ int sh[SB];
    const int t = threadIdx.x;
    sh[t] = (t < NSB) ? g_bsum[t] : 0;
    __syncthreads();
#pragma unroll
    for (int off = 1; off < SB; off <<= 1) {
        int u = (t >= off) ? sh[t - off] : 0;
        __syncthreads();
        if (t >= off) sh[t] += u;
        __syncthreads();
    }
    if (t < NSB) g_bsum[t] = (t == 0) ? 0 : sh[t - 1];   // exclusive
    if (t == 0) g_row_ptr[NN] = EE;
}

// Phase 3: row_ptr[i] = block_offset + local_inclusive - count; seed cursors.
__global__ __launch_bounds__(SB)
void scan_phase3() {
    const int i = blockIdx.x * SB + threadIdx.x;
    if (i >= NN) return;
    const int excl = g_bsum[blockIdx.x] + g_scan[i] - g_fill[i];
    g_row_ptr[i] = excl;
    g_fill[i]    = excl;   // fill cursor for permute
}

__global__ void permute_kernel(const void* __restrict__ rows_raw,
                               const void* __restrict__ cols_raw,
                               const float* __restrict__ vals) {
    int e = blockIdx.x * blockDim.x + threadIdx.x;
    if (e >= EE) return;
    int r = load_idx(rows_raw, e);
    int c = load_idx(cols_raw, e);
    int pos = atomicAdd(&g_fill[r], 1);
    g_ecol[pos] = c;
    g_eval[pos] = vals[e];
}

// One warp per node; lanes 0-23 each own a float4 of the feature row
// (one vector load per edge); all 32 lanes stage edge metadata + shfl.
// MODE 0: gather X (fp32),     own=X,    write bufA + h16B, out = e + n
// MODE 1: gather h16B (fp16),  own=bufA, write bufB + h16A, out += n
// MODE 2: gather h16A (fp16),  own=bufB, no writes,         out=(out+n)*0.25
template<int MODE>
__global__ __launch_bounds__(256)
void layer_kernel(const float* __restrict__ X, float* __restrict__ out) {
    const int node = (blockIdx.x * blockDim.x + threadIdx.x) >> 5;
    const int lane = threadIdx.x & 31;
    if (node >= NN) return;
    const bool act = lane < D4;          // 24 worker lanes

    const float4* __restrict__ Xf4 = reinterpret_cast<const float4*>(X);
    const uint2*  __restrict__ g16 = (MODE == 1) ? g_h16B : g_h16A;

    const int start = g_row_ptr[node];
    const int end   = g_row_ptr[node + 1];

    float4 a = make_float4(0.f, 0.f, 0.f, 0.f);
    for (int b = start; b < end; b += 32) {
        const int nb = end - b < 32 ? end - b : 32;
        int   ce = 0;
        float ve = 0.f;
        if (lane < nb) { ce = g_ecol[b + lane]; ve = g_eval[b + lane]; }
        for (int j = 0; j < nb; j++) {
            const int   c = __shfl_sync(0xffffffffu, ce, j);
            const float v = __shfl_sync(0xffffffffu, ve, j);
            if (act) {
                if (MODE == 0) {
                    const float4 m = __ldg(&Xf4[(size_t)c * D4 + lane]);
                    a.x = fmaf(v, m.x, a.x); a.y = fmaf(v, m.y, a.y);
                    a.z = fmaf(v, m.z, a.z); a.w = fmaf(v, m.w, a.w);
                } else {
                    const uint2 h = __ldg(&g16[(size_t)c * D4 + lane]);
                    const float2 f0 = __half22float2(*reinterpret_cast<const half2*>(&h.x));
                    const float2 f1 = __half22float2(*reinterpret_cast<const half2*>(&h.y));
                    a.x = fmaf(v, f0.x, a.x); a.y = fmaf(v, f0.y, a.y);
                    a.z = fmaf(v, f1.x, a.z); a.w = fmaf(v, f1.y, a.w);
                }
            }
        }
    }
    if (!act) return;

    // Own row (fp32) for gating.
    const float4* __restrict__ own4 =
        (MODE == 0) ? Xf4 : reinterpret_cast<const float4*>(MODE == 1 ? g_bufA
                                                                      : g_bufB);
    const size_t idx = (size_t)node * D4 + lane;
    const float4 e = __ldg(&own4[idx]);

    float4 n;
    n.x = fmaf(a.x, e.x, a.x); n.y = fmaf(a.y, e.y, a.y);
    n.z = fmaf(a.z, e.z, a.z); n.w = fmaf(a.w, e.w, a.w);

    if (MODE != 2) {
        float4* dstf = reinterpret_cast<float4*>(MODE == 0 ? g_bufA : g_bufB);
        dstf[idx] = n;
        const half2 lo = __floats2half2_rn(n.x, n.y);
        const half2 hi = __floats2half2_rn(n.z, n.w);
        uint2 hh;
        hh.x = *reinterpret_cast<const unsigned int*>(&lo);
        hh.y = *reinterpret_cast<const unsigned int*>(&hi);
        (MODE == 0 ? g_h16B : g_h16A)[idx] = hh;
    }

    float4* __restrict__ out4 = reinterpret_cast<float4*>(out);
    float4 o;
    if (MODE == 0) {
        o.x = e.x + n.x; o.y = e.y + n.y; o.z = e.z + n.z; o.w = e.w + n.w;
    } else {
        const float4 p = out4[idx];
        o.x = p.x + n.x; o.y = p.y + n.y; o.z = p.z + n.z; o.w = p.w + n.w;
    }
    if (MODE == 2) { o.x *= 0.25f; o.y *= 0.25f; o.z *= 0.25f; o.w *= 0.25f; }
    out4[idx] = o;
}

extern "C" void kernel_launch(void* const* d_in, const int* in_sizes, int n_in,
                              void* d_out, int out_size) {
    const float* X    = (const float*)d_in[0];
    const float* vals = (const float*)d_in[1];
    const void*  rows = d_in[2];
    const void*  cols = d_in[3];
    float* out = (float*)d_out;

    (void)in_sizes; (void)n_in; (void)out_size;

    // CSR build (once per call; reused by all 3 layers)
    zero_detect_kernel<<<(NN + 255) / 256, 256>>>((const unsigned int*)rows);
    hist_kernel<<<(EE + 255) / 256, 256>>>(rows);
    scan_phase1<<<NSB, SB>>>();
    scan_phase2<<<1, SB>>>();
    scan_phase3<<<NSB, SB>>>();
    permute_kernel<<<(EE + 255) / 256, 256>>>(rows, cols, vals);

    const int lgrid = (NN * 32 + 255) / 256;   // one warp per node
    layer_kernel<0><<<lgrid, 256>>>(X, out);
    layer_kernel<1><<<lgrid, 256>>>(X, out);
    layer_kernel<2><<<lgrid, 256>>>(X, out);
}

// round 17
// speedup vs baseline: 1.1024x; 1.1024x over previous
#include <cuda_runtime.h>

// ---------------------------------------------------------------------------
// GNN forward: 3 layers of COO SpMM + gating, mean over layers.
// R16: revert R15's fp16 shadow (kernel is L2-LATENCY-bound, not BW-bound;
// fp16 regressed). Instead raise MLP: inner edge loop padded to a multiple of
// 4 and hand-unrolled 4x, batching 12 independent LDGs in flight per warp
// before their FMAs. All-fp32 R14 structure otherwise.
// ---------------------------------------------------------------------------

namespace {
constexpr int NN  = 50000;     // nodes
constexpr int EE  = 800000;    // edges
constexpr int D   = 96;        // embedding dim
constexpr int SB  = 256;                       // scan block
constexpr int NSB = (NN + SB - 1) / SB;        // 196 scan blocks
}

// Scratch (allocation-free rule: __device__ globals only).
__device__ __align__(16) float g_bufA[(size_t)NN * D];
__device__ __align__(16) float g_bufB[(size_t)NN * D];
__device__ int   g_row_ptr[NN + 1];
__device__ int   g_fill[NN];          // counts, then fill cursors
__device__ int   g_scan[NN];          // block-local inclusive scans
__device__ int   g_bsum[NSB];         // per-block sums -> exclusive offsets
__device__ int   g_ecol[EE];
__device__ float g_eval[EE];
__device__ int   g_idx64;             // 1 if rows/cols are int64, 0 if int32

__device__ __forceinline__ int load_idx(const void* p, int e) {
    return g_idx64 ? (int)reinterpret_cast<const long long*>(p)[e]
                   : reinterpret_cast<const int*>(p)[e];
}

// Zero histogram counters; thread 0 also detects index width (JAX silently
// downcasts int64->int32 when x64 is off; int64 indices < 50000 have zero
// high words, random int32 data at odd u32 slots is ~never all zero).
__global__ void zero_detect_kernel(const unsigned int* __restrict__ rows_u32) {
    int i = blockIdx.x * blockDim.x + threadIdx.x;
    if (i < NN) g_fill[i] = 0;
    if (i == 0) {
        int is64 = 1;
        for (int k = 0; k < 64; k++)
            if (rows_u32[2 * k + 1] != 0u) { is64 = 0; break; }
        g_idx64 = is64;
    }
}

__global__ void hist_kernel(const void* __restrict__ rows_raw) {
    int e = blockIdx.x * blockDim.x + threadIdx.x;
    if (e < EE) atomicAdd(&g_fill[load_idx(rows_raw, e)], 1);
}

// Phase 1: block-local inclusive scan of counts; per-block totals to g_bsum.
__global__ __launch_bounds__(SB)
void scan_phase1() {
    __shared__ int sh[SB];
    const int t = threadIdx.x;
    const int i = blockIdx.x * SB + t;
    sh[t] = (i < NN) ? g_fill[i] : 0;
    __syncthreads();
#pragma unroll
    for (int off = 1; off < SB; off <<= 1) {
        int u = (t >= off) ? sh[t - off] : 0;
        __syncthreads();
        if (t >= off) sh[t] += u;
        __syncthreads();
    }
    if (i < NN) g_scan[i] = sh[t];
    if (t == SB - 1) g_bsum[blockIdx.x] = sh[t];
}

// Phase 2: exclusive scan of the NSB block sums (single tiny block).
__global__ __launch_bounds__(SB)
void scan_phase2() {
    __shared__ int sh[SB];
    const int t = threadIdx.x;
    sh[t] = (t < NSB) ? g_bsum[t] : 0;
    __syncthreads();
#pragma unroll
    for (int off = 1; off < SB; off <<= 1) {
        int u = (t >= off) ? sh[t - off] : 0;
        __syncthreads();
        if (t >= off) sh[t] += u;
        __syncthreads();
    }
    if (t < NSB) g_bsum[t] = (t == 0) ? 0 : sh[t - 1];   // exclusive
    if (t == 0) g_row_ptr[NN] = EE;
}

// Phase 3: row_ptr[i] = block_offset + local_inclusive - count; seed cursors.
__global__ __launch_bounds__(SB)
void scan_phase3() {
    const int i = blockIdx.x * SB + threadIdx.x;
    if (i >= NN) return;
    const int excl = g_bsum[blockIdx.x] + g_scan[i] - g_fill[i];
    g_row_ptr[i] = excl;
    g_fill[i]    = excl;   // fill cursor for permute
}

__global__ void permute_kernel(const void* __restrict__ rows_raw,
                               const void* __restrict__ cols_raw,
                               const float* __restrict__ vals) {
    int e = blockIdx.x * blockDim.x + threadIdx.x;
    if (e >= EE) return;
    int r = load_idx(rows_raw, e);
    int c = load_idx(cols_raw, e);
    int pos = atomicAdd(&g_fill[r], 1);
    g_ecol[pos] = c;
    g_eval[pos] = vals[e];
}

// One warp per node. Lane l accumulates dims {l, l+32, l+64}.
// Inner loop padded to a multiple of 4 edges (padding lanes hold c=0, v=0 ->
// contributes exactly 0) and unrolled 4x: 12 independent LDGs in flight.
// MODE 0: src = X,    dst = bufA, out = src_row + en
// MODE 1: src = bufA, dst = bufB, out += en
// MODE 2: src = bufB, no dst,     out = (out + en) * 0.25
template<int MODE>
__global__ __launch_bounds__(256)
void layer_kernel(const float* __restrict__ X, float* __restrict__ out) {
    const int node = (blockIdx.x * blockDim.x + threadIdx.x) >> 5;
    const int lane = threadIdx.x & 31;
    if (node >= NN) return;

    const float* __restrict__ src =
        (MODE == 0) ? X : (MODE == 1 ? g_bufA : g_bufB);
    float* __restrict__ dst = (MODE == 0) ? g_bufA : g_bufB;

    const int start = g_row_ptr[node];
    const int end   = g_row_ptr[node + 1];

    float a0 = 0.f, a1 = 0.f, a2 = 0.f;
    for (int b = start; b < end; b += 32) {
        const int nb = end - b < 32 ? end - b : 32;
        int   ce = 0;
        float ve = 0.f;
        if (lane < nb) { ce = g_ecol[b + lane]; ve = g_eval[b + lane]; }
        const int nb4 = (nb + 3) & ~3;   // pad; lanes >= nb carry c=0, v=0
        for (int j = 0; j < nb4; j += 4) {
            const int   c0 = __shfl_sync(0xffffffffu, ce, j);
            const int   c1 = __shfl_sync(0xffffffffu, ce, j + 1);
            const int   c2 = __shfl_sync(0xffffffffu, ce, j + 2);
            const int   c3 = __shfl_sync(0xffffffffu, ce, j + 3);
            const float v0 = __shfl_sync(0xffffffffu, ve, j);
            const float v1 = __shfl_sync(0xffffffffu, ve, j + 1);
            const float v2 = __shfl_sync(0xffffffffu, ve, j + 2);
            const float v3 = __shfl_sync(0xffffffffu, ve, j + 3);
            const float* __restrict__ r0 = src + (size_t)c0 * D + lane;
            const float* __restrict__ r1 = src + (size_t)c1 * D + lane;
            const float* __restrict__ r2 = src + (size_t)c2 * D + lane;
            const float* __restrict__ r3 = src + (size_t)c3 * D + lane;
            const float m00 = __ldg(r0), m01 = __ldg(r0 + 32), m02 = __ldg(r0 + 64);
            const float m10 = __ldg(r1), m11 = __ldg(r1 + 32), m12 = __ldg(r1 + 64);
            const float m20 = __ldg(r2), m21 = __ldg(r2 + 32), m22 = __ldg(r2 + 64);
            const float m30 = __ldg(r3), m31 = __ldg(r3 + 32), m32 = __ldg(r3 + 64);
            a0 = fmaf(v0, m00, a0); a1 = fmaf(v0, m01, a1); a2 = fmaf(v0, m02, a2);
            a0 = fmaf(v1, m10, a0); a1 = fmaf(v1, m11, a1); a2 = fmaf(v1, m12, a2);
            a0 = fmaf(v2, m20, a0); a1 = fmaf(v2, m21, a1); a2 = fmaf(v2, m22, a2);
            a0 = fmaf(v3, m30, a0); a1 = fmaf(v3, m31, a1); a2 = fmaf(v3, m32, a2);
        }
    }

    const float* __restrict__ my = src + (size_t)node * D;
    const float e0 = my[lane], e1 = my[lane + 32], e2 = my[lane + 64];
    const float n0 = fmaf(a0, e0, a0);
    const float n1 = fmaf(a1, e1, a1);
    const float n2 = fmaf(a2, e2, a2);

    const size_t o = (size_t)node * D;
    if (MODE != 2) {
        dst[o + lane] = n0; dst[o + lane + 32] = n1; dst[o + lane + 64] = n2;
    }
    float o0, o1, o2;
    if (MODE == 0) {
        o0 = e0 + n0; o1 = e1 + n1; o2 = e2 + n2;        // acc = X + ego1
    } else {
        o0 = out[o + lane] + n0;
        o1 = out[o + lane + 32] + n1;
        o2 = out[o + lane + 64] + n2;
    }
    if (MODE == 2) { o0 *= 0.25f; o1 *= 0.25f; o2 *= 0.25f; }
    out[o + lane] = o0; out[o + lane + 32] = o1; out[o + lane + 64] = o2;
}

extern "C" void kernel_launch(void* const* d_in, const int* in_sizes, int n_in,
                              void* d_out, int out_size) {
    const float* X    = (const float*)d_in[0];
    const float* vals = (const float*)d_in[1];
    const void*  rows = d_in[2];
    const void*  cols = d_in[3];
    float* out = (float*)d_out;

    (void)in_sizes; (void)n_in; (void)out_size;

    // CSR build (once per call; reused by all 3 layers)
    zero_detect_kernel<<<(NN + 255) / 256, 256>>>((const unsigned int*)rows);
    hist_kernel<<<(EE + 255) / 256, 256>>>(rows);
    scan_phase1<<<NSB, SB>>>();
    scan_phase2<<<1, SB>>>();
    scan_phase3<<<NSB, SB>>>();
    permute_kernel<<<(EE + 255) / 256, 256>>>(rows, cols, vals);

    const int lgrid = (NN * 32 + 255) / 256;   // one warp per node
    layer_kernel<0><<<lgrid, 256>>>(X, out);
    layer_kernel<1><<<lgrid, 256>>>(X, out);
    layer_kernel<2><<<lgrid, 256>>>(X, out);
}